// round 1
// baseline (speedup 1.0000x reference)
#include <cuda_runtime.h>
#include <math.h>

// RT-DETR post-processing: B=256 batches, Q=1000 queries, C=80 classes.
// Outputs (concatenated float32): scores[B,300] | labels[B,300] | boxes[B,300,4]

#define NB      256
#define NQ      1000
#define NC      80
#define SORT_N  1024
#define TOPK    300
#define THREADS 512
#define THRESH  0.05f

__global__ __launch_bounds__(THREADS, 2)
void rtdetr_post_kernel(const float* __restrict__ logits,
                        const float* __restrict__ boxes,
                        const float* __restrict__ tsizes,
                        float* __restrict__ out)
{
    __shared__ unsigned long long keys[SORT_N];

    const int b    = blockIdx.x;
    const int tid  = threadIdx.x;
    const int warp = tid >> 5;
    const int lane = tid & 31;
    const int NW   = THREADS / 32;

    const float* lg = logits + (size_t)b * NQ * NC;

    // ---- Phase 1: warp-per-query max+argmax over 80 logits, build sort keys ----
    for (int q = warp; q < SORT_N; q += NW) {
        if (q < NQ) {
            const float* row = lg + q * NC;
            float v  = -INFINITY;
            int   idx = 0x7fffffff;
            // Coalesced: lanes cover [0,32), [32,64), [64,80)
            float x0 = row[lane];
            if (x0 > v) { v = x0; idx = lane; }
            float x1 = row[lane + 32];
            if (x1 > v) { v = x1; idx = lane + 32; }
            if (lane < 16) {
                float x2 = row[lane + 64];
                if (x2 > v) { v = x2; idx = lane + 64; }
            }
            // Warp reduce: max value, ties -> lowest class index (jnp.argmax semantics)
            #pragma unroll
            for (int off = 16; off > 0; off >>= 1) {
                float ov = __shfl_down_sync(0xffffffffu, v, off);
                int   oi = __shfl_down_sync(0xffffffffu, idx, off);
                if (ov > v || (ov == v && oi < idx)) { v = ov; idx = oi; }
            }
            if (lane == 0) {
                float score = 1.0f / (1.0f + expf(-v));
                float ms    = (score > THRESH) ? score : -1.0f;
                // Order-preserving float->u32 (descending sort => bigger key wins)
                unsigned int bits = __float_as_uint(ms);
                unsigned int u = (bits & 0x80000000u) ? ~bits : (bits | 0x80000000u);
                // key: [score 32b | (0xFFFF - q) 16b  (=> ties pick lower q) | label 16b]
                unsigned long long key =
                    ((unsigned long long)u << 32) |
                    ((unsigned long long)(unsigned)(0xFFFF - q) << 16) |
                    (unsigned long long)(unsigned)idx;
                keys[q] = key;
            }
        } else {
            if (lane == 0) keys[q] = 0ull;  // below every real key
        }
    }
    __syncthreads();

    // ---- Phase 2: bitonic sort of 1024 u64 keys, descending ----
    #pragma unroll 1
    for (int k = 2; k <= SORT_N; k <<= 1) {
        #pragma unroll 1
        for (int j = k >> 1; j > 0; j >>= 1) {
            #pragma unroll
            for (int i = tid; i < SORT_N; i += THREADS) {
                int ixj = i ^ j;
                if (ixj > i) {
                    unsigned long long a = keys[i];
                    unsigned long long c = keys[ixj];
                    bool desc = ((i & k) == 0);
                    if (desc ? (a < c) : (a > c)) {
                        keys[i]   = c;
                        keys[ixj] = a;
                    }
                }
            }
            __syncthreads();
        }
    }

    // ---- Phase 3: decode top-300, gather + transform boxes, write outputs ----
    const float img_h = tsizes[2 * b + 0];
    const float img_w = tsizes[2 * b + 1];
    const int   S     = NB * TOPK;

    for (int i = tid; i < TOPK; i += THREADS) {
        unsigned long long key = keys[i];
        unsigned int u    = (unsigned int)(key >> 32);
        unsigned int bits = (u & 0x80000000u) ? (u ^ 0x80000000u) : ~u;
        float ms  = __uint_as_float(bits);
        int   q   = 0xFFFF - (int)((key >> 16) & 0xFFFFu);
        int   lab = (int)(key & 0xFFFFu);
        bool  valid = ms > THRESH;

        int o = b * TOPK + i;
        out[o]     = valid ? ms : 0.0f;
        out[S + o] = valid ? (float)lab : -1.0f;

        float4 bx = ((const float4*)boxes)[(size_t)b * NQ + q];
        float x0 = (bx.x - 0.5f * bx.z) * img_w;
        float y0 = (bx.y - 0.5f * bx.w) * img_h;
        float x1 = (bx.x + 0.5f * bx.z) * img_w;
        float y1 = (bx.y + 0.5f * bx.w) * img_h;
        float4 ob = valid ? make_float4(x0, y0, x1, y1)
                          : make_float4(0.f, 0.f, 0.f, 0.f);
        ((float4*)(out + 2 * S))[o] = ob;
    }
}

extern "C" void kernel_launch(void* const* d_in, const int* in_sizes, int n_in,
                              void* d_out, int out_size)
{
    const float* logits = (const float*)d_in[0];   // (256,1000,80) f32
    const float* boxes  = (const float*)d_in[1];   // (256,1000,4)  f32
    const float* tsizes = (const float*)d_in[2];   // (256,2)       f32
    float* out = (float*)d_out;                    // 460800 f32

    rtdetr_post_kernel<<<NB, THREADS>>>(logits, boxes, tsizes, out);
}

// round 2
// speedup vs baseline: 1.2557x; 1.2557x over previous
#include <cuda_runtime.h>
#include <math.h>

// RT-DETR post-processing, split into two kernels:
//   K1: per-query sigmoid-max/argmax over 80 classes -> packed u64 sort keys (HBM-bound)
//   K2: per-batch hybrid register/shfl bitonic sort of 1024 keys + emit (compute-bound)
// Output (concat f32): scores[256,300] | labels[256,300] | boxes[256,300,4]

#define NB      256
#define NQ      1000
#define NC      80
#define SORT_N  1024
#define TOPK    300
#define THRESH  0.05f

typedef unsigned long long u64;

// 2 MB scratch for packed keys (device global: allocation-free)
__device__ u64 g_keys[NB * SORT_N];

// ---------------------------------------------------------------------------
// Kernel 1: argmax + key build.  grid=(8,256), block=256 (8 warps, warp/query)
// ---------------------------------------------------------------------------
#define K1_CTAS 8
#define K1_QPC  (NQ / K1_CTAS)   // 125 queries per CTA

__global__ __launch_bounds__(256)
void k1_argmax(const float* __restrict__ logits)
{
    const int b    = blockIdx.y;
    const int warp = threadIdx.x >> 5;
    const int lane = threadIdx.x & 31;
    const int q0   = blockIdx.x * K1_QPC;

    const float* lg = logits + (size_t)b * NQ * NC;

    for (int q = q0 + warp; q < q0 + K1_QPC; q += 8) {
        const float4* row = (const float4*)(lg + q * NC);  // 20 float4 per row
        float v  = -INFINITY;
        int   idx = 0x7fffffff;
        if (lane < 20) {
            float4 x = row[lane];
            v = x.x; idx = lane * 4;
            if (x.y > v) { v = x.y; idx = lane * 4 + 1; }
            if (x.z > v) { v = x.z; idx = lane * 4 + 2; }
            if (x.w > v) { v = x.w; idx = lane * 4 + 3; }
        }
        #pragma unroll
        for (int off = 16; off > 0; off >>= 1) {
            float ov = __shfl_down_sync(0xffffffffu, v, off);
            int   oi = __shfl_down_sync(0xffffffffu, idx, off);
            if (ov > v || (ov == v && oi < idx)) { v = ov; idx = oi; }
        }
        if (lane == 0) {
            float score = 1.0f / (1.0f + expf(-v));
            float ms    = (score > THRESH) ? score : -1.0f;
            unsigned int bits = __float_as_uint(ms);
            unsigned int u = (bits & 0x80000000u) ? ~bits : (bits | 0x80000000u);
            // [score 32b | (0xFFFF - q) 16b (ties -> lower q) | label 16b]
            g_keys[b * SORT_N + q] =
                ((u64)u << 32) |
                ((u64)(unsigned)(0xFFFF - q) << 16) |
                (u64)(unsigned)idx;
        }
    }
}

// ---------------------------------------------------------------------------
// Kernel 2: hybrid bitonic sort (descending) + emit.  grid=256, block=512
// Thread t (warp w, lane l) owns elements e0 = 64w+l and e1 = e0+32.
// j<=32 steps are register/shfl (no barriers); j>=64 steps go through smem.
// ---------------------------------------------------------------------------
__device__ __forceinline__ u64 keep_mm(u64 v, u64 pv, bool kmax) {
    return kmax ? (v > pv ? v : pv) : (v < pv ? v : pv);
}

template<int K, int JSTART>
__device__ __forceinline__ void reg_merge(u64 &v0, u64 &v1, int e0, int e1)
{
    #pragma unroll
    for (int j = JSTART; j >= 1; j >>= 1) {
        if (j == 32) {
            // pair (e0, e1) lives in this thread; (e0&K)==(e1&K) here (K>=64)
            bool desc = ((e0 & K) == 0);
            if (desc ? (v0 < v1) : (v0 > v1)) { u64 t = v0; v0 = v1; v1 = t; }
        } else {
            u64 p0 = __shfl_xor_sync(0xffffffffu, v0, j);
            u64 p1 = __shfl_xor_sync(0xffffffffu, v1, j);
            bool desc0 = ((e0 & K) == 0);
            bool desc1 = ((e1 & K) == 0);
            bool low   = ((e0 & j) == 0);        // same for e1 (they differ in bit 5)
            v0 = keep_mm(v0, p0, desc0 == low);
            v1 = keep_mm(v1, p1, desc1 == low);
        }
    }
}

__device__ __forceinline__ void smem_step(u64* keys, int t, int j, int k)
{
    int i  = ((t & ~(j - 1)) << 1) | (t & (j - 1));
    int ix = i + j;
    u64 a = keys[i];
    u64 c = keys[ix];
    bool desc = ((i & k) == 0);
    if (desc ? (a < c) : (a > c)) { keys[i] = c; keys[ix] = a; }
}

__device__ __forceinline__ void emit_one(u64 key, int e, int b,
                                         float img_w, float img_h,
                                         const float* __restrict__ boxes,
                                         float* __restrict__ out)
{
    const int S = NB * TOPK;
    unsigned int u    = (unsigned int)(key >> 32);
    unsigned int bits = (u & 0x80000000u) ? (u ^ 0x80000000u) : ~u;
    float ms  = __uint_as_float(bits);
    int   q   = 0xFFFF - (int)((key >> 16) & 0xFFFFu);
    int   lab = (int)(key & 0xFFFFu);
    bool  valid = ms > THRESH;

    int o = b * TOPK + e;
    out[o]     = valid ? ms : 0.0f;
    out[S + o] = valid ? (float)lab : -1.0f;

    float4 bx = ((const float4*)boxes)[(size_t)b * NQ + q];
    float x0 = (bx.x - 0.5f * bx.z) * img_w;
    float y0 = (bx.y - 0.5f * bx.w) * img_h;
    float x1 = (bx.x + 0.5f * bx.z) * img_w;
    float y1 = (bx.y + 0.5f * bx.w) * img_h;
    ((float4*)(out + 2 * S))[o] = valid ? make_float4(x0, y0, x1, y1)
                                        : make_float4(0.f, 0.f, 0.f, 0.f);
}

__global__ __launch_bounds__(512)
void k2_sort_emit(const float* __restrict__ boxes,
                  const float* __restrict__ tsizes,
                  float* __restrict__ out)
{
    __shared__ u64 keys[SORT_N];

    const int b = blockIdx.x;
    const int t = threadIdx.x;
    const int w = t >> 5;
    const int l = t & 31;
    const int e0 = 64 * w + l;
    const int e1 = e0 + 32;

    const u64* gk = g_keys + (size_t)b * SORT_N;
    u64 v0 = (e0 < NQ) ? gk[e0] : 0ull;   // padding keys sort below all real keys
    u64 v1 = (e1 < NQ) ? gk[e1] : 0ull;

    // k = 2..64 entirely in registers (21 steps, zero barriers)
    reg_merge<2,  1 >(v0, v1, e0, e1);
    reg_merge<4,  2 >(v0, v1, e0, e1);
    reg_merge<8,  4 >(v0, v1, e0, e1);
    reg_merge<16, 8 >(v0, v1, e0, e1);
    reg_merge<32, 16>(v0, v1, e0, e1);
    reg_merge<64, 32>(v0, v1, e0, e1);
    keys[e0] = v0; keys[e1] = v1;
    __syncthreads();

    // k = 128
    smem_step(keys, t, 64, 128);  __syncthreads();
    v0 = keys[e0]; v1 = keys[e1];
    reg_merge<128, 32>(v0, v1, e0, e1);
    keys[e0] = v0; keys[e1] = v1;
    __syncthreads();

    // k = 256
    smem_step(keys, t, 128, 256); __syncthreads();
    smem_step(keys, t,  64, 256); __syncthreads();
    v0 = keys[e0]; v1 = keys[e1];
    reg_merge<256, 32>(v0, v1, e0, e1);
    keys[e0] = v0; keys[e1] = v1;
    __syncthreads();

    // k = 512
    smem_step(keys, t, 256, 512); __syncthreads();
    smem_step(keys, t, 128, 512); __syncthreads();
    smem_step(keys, t,  64, 512); __syncthreads();
    v0 = keys[e0]; v1 = keys[e1];
    reg_merge<512, 32>(v0, v1, e0, e1);
    keys[e0] = v0; keys[e1] = v1;
    __syncthreads();

    // k = 1024 (final, descending)
    smem_step(keys, t, 512, 1024); __syncthreads();
    smem_step(keys, t, 256, 1024); __syncthreads();
    smem_step(keys, t, 128, 1024); __syncthreads();
    smem_step(keys, t,  64, 1024); __syncthreads();
    v0 = keys[e0]; v1 = keys[e1];
    reg_merge<1024, 32>(v0, v1, e0, e1);

    // Emit top-300 directly from registers (sorted: element index == rank)
    const float img_h = tsizes[2 * b + 0];
    const float img_w = tsizes[2 * b + 1];
    if (e0 < TOPK) emit_one(v0, e0, b, img_w, img_h, boxes, out);
    if (e1 < TOPK) emit_one(v1, e1, b, img_w, img_h, boxes, out);
}

// ---------------------------------------------------------------------------
extern "C" void kernel_launch(void* const* d_in, const int* in_sizes, int n_in,
                              void* d_out, int out_size)
{
    const float* logits = (const float*)d_in[0];   // (256,1000,80) f32
    const float* boxes  = (const float*)d_in[1];   // (256,1000,4)  f32
    const float* tsizes = (const float*)d_in[2];   // (256,2)       f32
    float* out = (float*)d_out;                    // 460800 f32

    dim3 g1(K1_CTAS, NB);
    k1_argmax<<<g1, 256>>>(logits);
    k2_sort_emit<<<NB, 512>>>(boxes, tsizes, out);
}

// round 5
// speedup vs baseline: 2.2432x; 1.7864x over previous
#include <cuda_runtime.h>
#include <math.h>

// RT-DETR post-processing, three kernels:
//   K1 : per-query sigmoid-max/argmax (REDUX-based, 4 queries/warp) -> u64 keys
//   K2a: per (batch, half) bitonic sort of 512 keys (desc / asc)
//   K2b: bitonic merge of the two sorted halves + emit top-300
// Output (concat f32): scores[256,300] | labels[256,300] | boxes[256,300,4]

#define NB      256
#define NQ      1000
#define NC      80
#define SORT_N  1024
#define TOPK    300
#define THRESH  0.05f

typedef unsigned long long u64;
typedef unsigned int       u32;

__device__ u64 g_keys[NB * SORT_N];   // 2 MB scratch

__device__ __forceinline__ u32 f2ord(u32 b) {            // order-preserving f32->u32
    return (b & 0x80000000u) ? ~b : (b | 0x80000000u);
}
__device__ __forceinline__ u32 ord2f(u32 u) {
    return (u & 0x80000000u) ? (u ^ 0x80000000u) : ~u;
}

// ---------------------------------------------------------------------------
// K1: grid=8000, block=256 (8 warps); each warp handles 4 consecutive queries.
// ---------------------------------------------------------------------------
__global__ __launch_bounds__(256)
void k1_argmax(const float* __restrict__ logits)
{
    const int warp = threadIdx.x >> 5;
    const int lane = threadIdx.x & 31;
    const int f0   = (blockIdx.x * 8 + warp) * 4;     // first flat query (b*NQ+q)

    const float4* base = (const float4*)logits + (size_t)f0 * (NC / 4);

    u32 u[4]; int id[4];
    #pragma unroll
    for (int j = 0; j < 4; j++) { u[j] = 0u; id[j] = 1023; }

    if (lane < NC / 4) {                              // 20 lanes carry data
        #pragma unroll
        for (int j = 0; j < 4; j++) {                 // 4 independent LDG.128
            float4 x = base[j * (NC / 4) + lane];
            float v = x.x; int idx = lane * 4;
            if (x.y > v) { v = x.y; idx = lane * 4 + 1; }
            if (x.z > v) { v = x.z; idx = lane * 4 + 2; }
            if (x.w > v) { v = x.w; idx = lane * 4 + 3; }
            u[j]  = f2ord(__float_as_uint(v));
            id[j] = idx;
        }
    }

    u32 m[4], am[4];
    #pragma unroll
    for (int j = 0; j < 4; j++) {
        m[j] = __reduce_max_sync(0xffffffffu, u[j]);
        u32 cand = (u[j] == m[j]) ? (u32)id[j] : 1023u;   // ties -> lowest class
        am[j] = __reduce_min_sync(0xffffffffu, cand);
    }

    if (lane < 4) {   // lanes 0..3 finalize one query each (coalesced 32B store)
        u32 mm = (lane == 0) ? m[0]  : (lane == 1) ? m[1]  : (lane == 2) ? m[2]  : m[3];
        u32 aa = (lane == 0) ? am[0] : (lane == 1) ? am[1] : (lane == 2) ? am[2] : am[3];
        float v     = __uint_as_float(ord2f(mm));
        float score = 1.0f / (1.0f + expf(-v));
        float ms    = (score > THRESH) ? score : -1.0f;
        u32 sbits   = f2ord(__float_as_uint(ms));
        int f = f0 + lane;
        int b = f / NQ;
        int q = f - b * NQ;
        // [score 32b | (0xFFFF - q) 16b (ties -> lower q) | label 16b]
        g_keys[b * SORT_N + q] = ((u64)sbits << 32)
                               | ((u64)(u32)(0xFFFF - q) << 16)
                               | (u64)aa;
    }
}

// ---------------------------------------------------------------------------
// Bitonic helpers (hybrid register/shfl + smem)
// ---------------------------------------------------------------------------
__device__ __forceinline__ u64 keep_mm(u64 v, u64 pv, bool kmax) {
    return kmax ? (v > pv ? v : pv) : (v < pv ? v : pv);
}

template<int K, int JSTART>
__device__ __forceinline__ void reg_merge(u64 &v0, u64 &v1, int e0, int e1, bool asc)
{
    #pragma unroll
    for (int j = JSTART; j >= 1; j >>= 1) {
        if (j == 32) {
            bool desc = (((e0 & K) == 0) != asc);
            if (desc ? (v0 < v1) : (v0 > v1)) { u64 t = v0; v0 = v1; v1 = t; }
        } else {
            u64 p0 = __shfl_xor_sync(0xffffffffu, v0, j);
            u64 p1 = __shfl_xor_sync(0xffffffffu, v1, j);
            bool desc0 = (((e0 & K) == 0) != asc);
            bool desc1 = (((e1 & K) == 0) != asc);
            bool low   = ((e0 & j) == 0);
            v0 = keep_mm(v0, p0, desc0 == low);
            v1 = keep_mm(v1, p1, desc1 == low);
        }
    }
}

__device__ __forceinline__ void smem_step(u64* keys, int t, int j, int k, bool asc)
{
    int i  = ((t & ~(j - 1)) << 1) | (t & (j - 1));
    int ix = i + j;
    u64 a = keys[i];
    u64 c = keys[ix];
    bool desc = (((i & k) == 0) != asc);
    if (desc ? (a < c) : (a > c)) { keys[i] = c; keys[ix] = a; }
}

// ---------------------------------------------------------------------------
// K2a: grid=(2, 256), block=256. Sorts 512 keys; half 0 desc, half 1 asc.
// Thread t (warp w 0..7, lane l) owns local elements e0=64w+l, e1=e0+32.
// ---------------------------------------------------------------------------
__global__ __launch_bounds__(256)
void k2a_sort512()
{
    __shared__ u64 keys[512];

    const int  h   = blockIdx.x;          // half
    const int  b   = blockIdx.y;
    const bool asc = (h == 1);
    const int  t   = threadIdx.x;
    const int  w   = t >> 5;
    const int  l   = t & 31;
    const int  e0  = 64 * w + l;
    const int  e1  = e0 + 32;

    u64* gk = g_keys + (size_t)b * SORT_N + h * 512;

    int f0 = h * 512 + e0, f1 = h * 512 + e1;
    u64 v0 = (f0 < NQ) ? gk[e0] : 0ull;   // padding below all real keys
    u64 v1 = (f1 < NQ) ? gk[e1] : 0ull;

    reg_merge<2,  1 >(v0, v1, e0, e1, asc);
    reg_merge<4,  2 >(v0, v1, e0, e1, asc);
    reg_merge<8,  4 >(v0, v1, e0, e1, asc);
    reg_merge<16, 8 >(v0, v1, e0, e1, asc);
    reg_merge<32, 16>(v0, v1, e0, e1, asc);
    reg_merge<64, 32>(v0, v1, e0, e1, asc);
    keys[e0] = v0; keys[e1] = v1;
    __syncthreads();

    smem_step(keys, t, 64, 128, asc);  __syncthreads();
    v0 = keys[e0]; v1 = keys[e1];
    reg_merge<128, 32>(v0, v1, e0, e1, asc);
    keys[e0] = v0; keys[e1] = v1;
    __syncthreads();

    smem_step(keys, t, 128, 256, asc); __syncthreads();
    smem_step(keys, t,  64, 256, asc); __syncthreads();
    v0 = keys[e0]; v1 = keys[e1];
    reg_merge<256, 32>(v0, v1, e0, e1, asc);
    keys[e0] = v0; keys[e1] = v1;
    __syncthreads();

    smem_step(keys, t, 256, 512, asc); __syncthreads();
    smem_step(keys, t, 128, 512, asc); __syncthreads();
    smem_step(keys, t,  64, 512, asc); __syncthreads();
    v0 = keys[e0]; v1 = keys[e1];
    reg_merge<512, 32>(v0, v1, e0, e1, asc);

    gk[e0] = v0; gk[e1] = v1;             // fully sorted (desc or asc)
}

// ---------------------------------------------------------------------------
// K2b: grid=256, block=512. Merge desc||asc (bitonic) -> desc, emit top-300.
// ---------------------------------------------------------------------------
__device__ __forceinline__ void emit_one(u64 key, int e, int b,
                                         float img_w, float img_h,
                                         const float* __restrict__ boxes,
                                         float* __restrict__ out)
{
    const int S = NB * TOPK;
    u32 u    = (u32)(key >> 32);
    float ms = __uint_as_float(ord2f(u));
    int q    = 0xFFFF - (int)((key >> 16) & 0xFFFFu);
    int lab  = (int)(key & 0xFFFFu);
    bool valid = ms > THRESH;

    int o = b * TOPK + e;
    out[o]     = valid ? ms : 0.0f;
    out[S + o] = valid ? (float)lab : -1.0f;

    float4 bx = ((const float4*)boxes)[(size_t)b * NQ + q];
    float x0 = (bx.x - 0.5f * bx.z) * img_w;
    float y0 = (bx.y - 0.5f * bx.w) * img_h;
    float x1 = (bx.x + 0.5f * bx.z) * img_w;
    float y1 = (bx.y + 0.5f * bx.w) * img_h;
    ((float4*)(out + 2 * S))[o] = valid ? make_float4(x0, y0, x1, y1)
                                        : make_float4(0.f, 0.f, 0.f, 0.f);
}

__global__ __launch_bounds__(512)
void k2b_merge_emit(const float* __restrict__ boxes,
                    const float* __restrict__ tsizes,
                    float* __restrict__ out)
{
    __shared__ u64 keys[SORT_N];

    const int b = blockIdx.x;
    const int t = threadIdx.x;
    const int w = t >> 5;
    const int l = t & 31;
    const int e0 = 64 * w + l;
    const int e1 = e0 + 32;

    const u64* gk = g_keys + (size_t)b * SORT_N;

    // j=512 merge step fused into the global->smem load (k=1024, all desc)
    {
        u64 a = gk[t];
        u64 c = gk[t + 512];
        if (a < c) { u64 tmp = a; a = c; c = tmp; }
        keys[t] = a; keys[t + 512] = c;
    }
    __syncthreads();

    smem_step(keys, t, 256, 1024, false); __syncthreads();
    smem_step(keys, t, 128, 1024, false); __syncthreads();
    smem_step(keys, t,  64, 1024, false); __syncthreads();

    u64 v0 = keys[e0], v1 = keys[e1];
    reg_merge<1024, 32>(v0, v1, e0, e1, false);

    const float img_h = tsizes[2 * b + 0];
    const float img_w = tsizes[2 * b + 1];
    if (e0 < TOPK) emit_one(v0, e0, b, img_w, img_h, boxes, out);
    if (e1 < TOPK) emit_one(v1, e1, b, img_w, img_h, boxes, out);
}

// ---------------------------------------------------------------------------
extern "C" void kernel_launch(void* const* d_in, const int* in_sizes, int n_in,
                              void* d_out, int out_size)
{
    const float* logits = (const float*)d_in[0];   // (256,1000,80) f32
    const float* boxes  = (const float*)d_in[1];   // (256,1000,4)  f32
    const float* tsizes = (const float*)d_in[2];   // (256,2)       f32
    float* out = (float*)d_out;                    // 460800 f32

    k1_argmax<<<8000, 256>>>(logits);
    k2a_sort512<<<dim3(2, NB), 256>>>();
    k2b_merge_emit<<<NB, 512>>>(boxes, tsizes, out);
}